// round 1
// baseline (speedup 1.0000x reference)
#include <cuda_runtime.h>
#include <cstdint>

// Problem: x (8,32,512,512) fp32. Output = (dilated, eroded):
//   dilated = 3x3 sliding max (replicate border), eroded = 3x3 sliding min.
// d_out holds dilated [N] followed by eroded [N], N = 8*32*512*512.
//
// Strategy: one block per (image, 64-row strip). 128 threads x float4 cover
// the whole W=512 row. Each row is read from GMEM once; horizontal 3-window
// min/max computed with smem neighbor exchange; vertical 3-window rolled in
// registers. Both outputs produced from a single read stream -> HBM-bound
// at ~1.03x read + 2x write amplification.

#define W 512
#define H 512
#define TPB 128          // threads per block, each owns 4 columns
#define ROWS 64          // rows per strip

__device__ __forceinline__ float min3f(float a, float b, float c) {
    return fminf(a, fminf(b, c));
}
__device__ __forceinline__ float max3f(float a, float b, float c) {
    return fmaxf(a, fmaxf(b, c));
}

__global__ __launch_bounds__(TPB)
void morpho33_kernel(const float* __restrict__ x,
                     float* __restrict__ dil,
                     float* __restrict__ ero)
{
    const int nc = blockIdx.x;                 // which (n,c) image: 0..255
    const int r0 = blockIdx.y * ROWS;          // first output row of this strip

    const float* __restrict__ img = x   + (size_t)nc * (H * W);
    float* __restrict__ dimg       = dil + (size_t)nc * (H * W);
    float* __restrict__ eimg       = ero + (size_t)nc * (H * W);

    __shared__ float srow[2][W];               // double-buffered row exchange

    const int tid = threadIdx.x;
    const int c0  = tid * 4;                   // first column this thread owns

    // Rolling horizontal min/max for rows r-1 (P), r (C), r+1 (N)
    float hminP[4], hmaxP[4], hminC[4], hmaxC[4];

    int buf = 0;

    // --- load one (clamped) row, produce horizontal 3-window min/max ---
    auto load_hrow = [&](int r, float hmin[4], float hmax[4]) {
        int rc = r < 0 ? 0 : (r >= H ? H - 1 : r);
        float4 v = *reinterpret_cast<const float4*>(img + (size_t)rc * W + c0);
        float* s = srow[buf];
        *reinterpret_cast<float4*>(s + c0) = v;   // aligned STS.128
        __syncthreads();
        // neighbor elements across thread boundary, clamped (replicate border)
        float left  = s[c0 == 0 ? 0 : c0 - 1];
        float right = s[c0 + 4 >= W ? W - 1 : c0 + 4];
        float a0 = left, a1 = v.x, a2 = v.y, a3 = v.z, a4 = v.w, a5 = right;
        hmin[0] = min3f(a0, a1, a2);  hmax[0] = max3f(a0, a1, a2);
        hmin[1] = min3f(a1, a2, a3);  hmax[1] = max3f(a1, a2, a3);
        hmin[2] = min3f(a2, a3, a4);  hmax[2] = max3f(a2, a3, a4);
        hmin[3] = min3f(a3, a4, a5);  hmax[3] = max3f(a3, a4, a5);
        buf ^= 1;
    };

    // prologue: rows r0-1 (clamped) and r0
    load_hrow(r0 - 1, hminP, hmaxP);
    load_hrow(r0,     hminC, hmaxC);

    #pragma unroll 4
    for (int r = r0; r < r0 + ROWS; ++r) {
        float hminN[4], hmaxN[4];
        load_hrow(r + 1, hminN, hmaxN);        // clamps at H-1 for last row

        float4 dv, ev;
        dv.x = max3f(hmaxP[0], hmaxC[0], hmaxN[0]);
        dv.y = max3f(hmaxP[1], hmaxC[1], hmaxN[1]);
        dv.z = max3f(hmaxP[2], hmaxC[2], hmaxN[2]);
        dv.w = max3f(hmaxP[3], hmaxC[3], hmaxN[3]);
        ev.x = min3f(hminP[0], hminC[0], hminN[0]);
        ev.y = min3f(hminP[1], hminC[1], hminN[1]);
        ev.z = min3f(hminP[2], hminC[2], hminN[2]);
        ev.w = min3f(hminP[3], hminC[3], hminN[3]);

        *reinterpret_cast<float4*>(dimg + (size_t)r * W + c0) = dv;
        *reinterpret_cast<float4*>(eimg + (size_t)r * W + c0) = ev;

        #pragma unroll
        for (int j = 0; j < 4; ++j) {
            hminP[j] = hminC[j];  hmaxP[j] = hmaxC[j];
            hminC[j] = hminN[j];  hmaxC[j] = hmaxN[j];
        }
    }
}

extern "C" void kernel_launch(void* const* d_in, const int* in_sizes, int n_in,
                              void* d_out, int out_size)
{
    const float* x = (const float*)d_in[0];
    float* out = (float*)d_out;
    const int n = in_sizes[0];                 // 8*32*512*512
    const int nimg = n / (H * W);              // 256 images

    float* dil = out;                          // dilated first
    float* ero = out + (size_t)n;              // then eroded

    dim3 grid(nimg, H / ROWS);                 // 256 x 8 = 2048 blocks
    morpho33_kernel<<<grid, TPB>>>(x, dil, ero);
}

// round 6
// speedup vs baseline: 1.0132x; 1.0132x over previous
#include <cuda_runtime.h>
#include <cstdint>

// x (8,32,512,512) fp32 -> (dilated, eroded) = 3x3 sliding max/min, replicate border.
// d_out = dilated[N] ++ eroded[N].
//
// Barrier-free version: each thread loads its float4 plus 2 redundant scalar
// halo floats straight from GMEM (same 128B lines => no extra DRAM traffic).
// No smem, no __syncthreads. Unroll-8 row loop exposes many independent LDGs
// per warp so DRAM latency is hidden. Streaming stores (__stcs) keep L2 for
// the input halo rows shared across adjacent strips.

#define W 512
#define H 512
#define TPB 128          // threads per block, each owns 4 contiguous columns
#define ROWS 64          // output rows per block strip

__device__ __forceinline__ float min3f(float a, float b, float c) {
    return fminf(a, fminf(b, c));
}
__device__ __forceinline__ float max3f(float a, float b, float c) {
    return fmaxf(a, fmaxf(b, c));
}

__global__ __launch_bounds__(TPB)
void morpho33_kernel(const float* __restrict__ x,
                     float* __restrict__ dil,
                     float* __restrict__ ero)
{
    const int nc = blockIdx.x;                 // image index 0..255
    const int r0 = blockIdx.y * ROWS;          // first output row of strip

    const int c0 = threadIdx.x * 4;
    const int cl = (c0 == 0)       ? 0     : c0 - 1;   // left halo col (clamped)
    const int cr = (c0 + 4 >= W)   ? W - 1 : c0 + 4;   // right halo col (clamped)

    const float* __restrict__ img = x + (size_t)nc * (H * W);
    // Additive row pointers for the two output streams (stride W floats/row).
    float* dptr = dil + (size_t)nc * (H * W) + (size_t)r0 * W + c0;
    float* eptr = ero + (size_t)nc * (H * W) + (size_t)r0 * W + c0;

    float hminP[4], hmaxP[4], hminC[4], hmaxC[4];

    // load one clamped row, produce horizontal 3-window min/max (no smem, no BAR)
    auto load_hrow = [&](int r, float hmin[4], float hmax[4]) {
        const int rc = r < 0 ? 0 : (r >= H ? H - 1 : r);
        const float* row = img + (size_t)rc * W;
        float4 v    = *reinterpret_cast<const float4*>(row + c0);
        float left  = row[cl];
        float right = row[cr];
        hmin[0] = min3f(left, v.x, v.y);  hmax[0] = max3f(left, v.x, v.y);
        hmin[1] = min3f(v.x, v.y, v.z);   hmax[1] = max3f(v.x, v.y, v.z);
        hmin[2] = min3f(v.y, v.z, v.w);   hmax[2] = max3f(v.y, v.z, v.w);
        hmin[3] = min3f(v.z, v.w, right); hmax[3] = max3f(v.z, v.w, right);
    };

    // prologue: rows r0-1 (clamped) and r0
    load_hrow(r0 - 1, hminP, hmaxP);
    load_hrow(r0,     hminC, hmaxC);

    #pragma unroll 8
    for (int r = r0; r < r0 + ROWS; ++r) {
        float hminN[4], hmaxN[4];
        load_hrow(r + 1, hminN, hmaxN);        // clamps at H-1 on last row

        float4 dv, ev;
        dv.x = max3f(hmaxP[0], hmaxC[0], hmaxN[0]);
        dv.y = max3f(hmaxP[1], hmaxC[1], hmaxN[1]);
        dv.z = max3f(hmaxP[2], hmaxC[2], hmaxN[2]);
        dv.w = max3f(hmaxP[3], hmaxC[3], hmaxN[3]);
        ev.x = min3f(hminP[0], hminC[0], hminN[0]);
        ev.y = min3f(hminP[1], hminC[1], hminN[1]);
        ev.z = min3f(hminP[2], hminC[2], hminN[2]);
        ev.w = min3f(hminP[3], hminC[3], hminN[3]);

        __stcs(reinterpret_cast<float4*>(dptr), dv);
        __stcs(reinterpret_cast<float4*>(eptr), ev);
        dptr += W;
        eptr += W;

        #pragma unroll
        for (int j = 0; j < 4; ++j) {
            hminP[j] = hminC[j];  hmaxP[j] = hmaxC[j];
            hminC[j] = hminN[j];  hmaxC[j] = hmaxN[j];
        }
    }
}

extern "C" void kernel_launch(void* const* d_in, const int* in_sizes, int n_in,
                              void* d_out, int out_size)
{
    const float* x = (const float*)d_in[0];
    float* out = (float*)d_out;
    const int n = in_sizes[0];                 // 8*32*512*512
    const int nimg = n / (H * W);              // 256 images

    float* dil = out;
    float* ero = out + (size_t)n;

    dim3 grid(nimg, H / ROWS);                 // 256 x 8 = 2048 blocks
    morpho33_kernel<<<grid, TPB>>>(x, dil, ero);
}

// round 15
// speedup vs baseline: 1.1384x; 1.1235x over previous
#include <cuda_runtime.h>
#include <cstdint>

// x (8,32,512,512) fp32 -> (dilated, eroded) = 3x3 sliding max/min, replicate border.
// d_out = dilated[N] ++ eroded[N].
//
// R6: explicit depth-2 software pipeline (load row r+2 while finishing row r)
// + warp-shuffle halo exchange (only lanes 0/31 issue a predicated scalar LDG).
// Diagnosed limiter was latency exposure: regs=48 prevented ptxas from
// batching loads, MLP_eff~1. Pipeline + unroll-4 + 64-reg budget forces
// multiple independent row loads in flight per warp.

#define W 512
#define H 512
#define TPB 128          // 4 warps; each thread owns 4 contiguous columns
#define ROWS 64          // output rows per block strip

struct Raw { float4 v; float lb, rb; };

__device__ __forceinline__ float min3f(float a, float b, float c) {
    return fminf(a, fminf(b, c));
}
__device__ __forceinline__ float max3f(float a, float b, float c) {
    return fmaxf(a, fmaxf(b, c));
}

__device__ __forceinline__ Raw load_raw(const float* __restrict__ img,
                                        int r, int c0, int lane)
{
    const int rc = r < 0 ? 0 : (r >= H ? H - 1 : r);
    const float* row = img + (size_t)rc * W;
    Raw o;
    o.v = *reinterpret_cast<const float4*>(row + c0);
    o.lb = 0.f; o.rb = 0.f;
    if (lane == 0  && c0 > 0)     o.lb = row[c0 - 1];   // predicated, 1 lane
    if (lane == 31 && c0 + 4 < W) o.rb = row[c0 + 4];   // predicated, 1 lane
    return o;
}

__device__ __forceinline__ void hcompute(const Raw& rw, int lane, int c0,
                                         float hmin[4], float hmax[4])
{
    // cross-lane neighbor exchange (whole row is warp-contiguous: warp covers
    // 128 consecutive floats)
    float l_sh = __shfl_up_sync(0xffffffffu, rw.v.w, 1);
    float r_sh = __shfl_down_sync(0xffffffffu, rw.v.x, 1);
    float left  = (lane == 0)  ? ((c0 == 0)     ? rw.v.x : rw.lb) : l_sh;
    float right = (lane == 31) ? ((c0 + 4 >= W) ? rw.v.w : rw.rb) : r_sh;

    hmin[0] = min3f(left,  rw.v.x, rw.v.y);  hmax[0] = max3f(left,  rw.v.x, rw.v.y);
    hmin[1] = min3f(rw.v.x, rw.v.y, rw.v.z); hmax[1] = max3f(rw.v.x, rw.v.y, rw.v.z);
    hmin[2] = min3f(rw.v.y, rw.v.z, rw.v.w); hmax[2] = max3f(rw.v.y, rw.v.z, rw.v.w);
    hmin[3] = min3f(rw.v.z, rw.v.w, right);  hmax[3] = max3f(rw.v.z, rw.v.w, right);
}

__global__ __launch_bounds__(TPB, 8)
void morpho33_kernel(const float* __restrict__ x,
                     float* __restrict__ dil,
                     float* __restrict__ ero)
{
    const int nc = blockIdx.x;                 // image index 0..255
    const int r0 = blockIdx.y * ROWS;          // first output row of strip

    const int lane = threadIdx.x & 31;
    const int c0   = threadIdx.x * 4;

    const float* __restrict__ img = x + (size_t)nc * (H * W);
    float* dptr = dil + (size_t)nc * (H * W) + (size_t)r0 * W + c0;
    float* eptr = ero + (size_t)nc * (H * W) + (size_t)r0 * W + c0;

    float hminP[4], hmaxP[4], hminC[4], hmaxC[4];

    // prologue: rows r0-1, r0 computed; row r0+1 raw data prefetched
    {
        Raw a = load_raw(img, r0 - 1, c0, lane);
        Raw b = load_raw(img, r0,     c0, lane);
        hcompute(a, lane, c0, hminP, hmaxP);
        hcompute(b, lane, c0, hminC, hmaxC);
    }
    Raw rawNext = load_raw(img, r0 + 1, c0, lane);   // row r+1 data

    #pragma unroll 4
    for (int r = r0; r < r0 + ROWS; ++r) {
        // prefetch row r+2 (clamped); consumed next iteration -> loads of 4
        // unrolled iterations batch into independent LDGs (MLP ~4-6)
        Raw rawFut = load_raw(img, r + 2, c0, lane);

        float hminN[4], hmaxN[4];
        hcompute(rawNext, lane, c0, hminN, hmaxN);

        float4 dv, ev;
        dv.x = max3f(hmaxP[0], hmaxC[0], hmaxN[0]);
        dv.y = max3f(hmaxP[1], hmaxC[1], hmaxN[1]);
        dv.z = max3f(hmaxP[2], hmaxC[2], hmaxN[2]);
        dv.w = max3f(hmaxP[3], hmaxC[3], hmaxN[3]);
        ev.x = min3f(hminP[0], hminC[0], hminN[0]);
        ev.y = min3f(hminP[1], hminC[1], hminN[1]);
        ev.z = min3f(hminP[2], hminC[2], hminN[2]);
        ev.w = min3f(hminP[3], hminC[3], hminN[3]);

        __stcs(reinterpret_cast<float4*>(dptr), dv);
        __stcs(reinterpret_cast<float4*>(eptr), ev);
        dptr += W;
        eptr += W;

        #pragma unroll
        for (int j = 0; j < 4; ++j) {
            hminP[j] = hminC[j];  hmaxP[j] = hmaxC[j];
            hminC[j] = hminN[j];  hmaxC[j] = hmaxN[j];
        }
        rawNext = rawFut;
    }
}

extern "C" void kernel_launch(void* const* d_in, const int* in_sizes, int n_in,
                              void* d_out, int out_size)
{
    const float* x = (const float*)d_in[0];
    float* out = (float*)d_out;
    const int n = in_sizes[0];                 // 8*32*512*512
    const int nimg = n / (H * W);              // 256 images

    float* dil = out;
    float* ero = out + (size_t)n;

    dim3 grid(nimg, H / ROWS);                 // 256 x 8 = 2048 blocks
    morpho33_kernel<<<grid, TPB>>>(x, dil, ero);
}